// round 16
// baseline (speedup 1.0000x reference)
#include <cuda_runtime.h>
#include <cuda_bf16.h>
#include <cstdint>
#include <cstddef>

// Problem constants
#define BB   16
#define SS   4096
#define DD   512
#define KK   256
#define BS   65536
#define QSIZE 33554432
#define FULLOUT (QSIZE + 1 + BS + BB*2)

#define MARGIN 1.0f

// ---------------------------------------------------------------------------
// device scratch (no cudaMalloc allowed)
__device__ float g_partial[1024 * DD];     // per-main-block pooled partials
__device__ float g_weights[BB * 2];
__device__ float g_c2half[KK];             // 0.5||c||^2 (exact rescore)
__device__ float g_scOff[KK];              // sum(m*c/s) + 0.5||c||^2 (approx score)
__device__ __align__(16) float g_instd[DD];
__device__ float g_lossU;
__device__ float g_lossK;
__device__ int   g_done;
__device__ int   g_sidx[BS];
__device__ __align__(16) __nv_bfloat16 g_cbB[KK * DD];  // bf16(cb/std)
__device__ __align__(16) float g_cbD[KK * DD];          // denormalized codebook

// ---------------------------------------------------------------------------
__device__ __forceinline__ uint32_t pack_bf16(float a, float b) {
    uint32_t r;
    asm("cvt.rn.bf16x2.f32 %0, %1, %2;" : "=r"(r) : "f"(b), "f"(a));
    return r;
}
__device__ __forceinline__ void mma_bf16(float c[4], const uint32_t a[4], const uint32_t b[2]) {
    asm volatile("mma.sync.aligned.m16n8k16.row.col.f32.bf16.bf16.f32 "
        "{%0,%1,%2,%3}, {%4,%5,%6,%7}, {%8,%9}, {%0,%1,%2,%3};"
        : "+f"(c[0]), "+f"(c[1]), "+f"(c[2]), "+f"(c[3])
        : "r"(a[0]), "r"(a[1]), "r"(a[2]), "r"(a[3]), "r"(b[0]), "r"(b[1]));
}
__device__ __forceinline__ void ldmatrix_x4(uint32_t r[4], uint32_t saddr) {
    asm volatile("ldmatrix.sync.aligned.m8n8.x4.shared.b16 {%0,%1,%2,%3}, [%4];"
        : "=r"(r[0]), "=r"(r[1]), "=r"(r[2]), "=r"(r[3]) : "r"(saddr));
}
__device__ __forceinline__ void ldmatrix_x2(uint32_t r[2], uint32_t saddr) {
    asm volatile("ldmatrix.sync.aligned.m8n8.x2.shared.b16 {%0,%1}, [%2];"
        : "=r"(r[0]), "=r"(r[1]) : "r"(saddr));
}
__device__ __forceinline__ uint32_t smem_u32(const void* p) {
    uint32_t a;
    asm("{ .reg .u64 t; cvta.to.shared.u64 t, %1; cvt.u32.u64 %0, t; }" : "=r"(a) : "l"(p));
    return a;
}
__device__ __forceinline__ void cp_async16(uint32_t saddr, const void* g) {
    asm volatile("cp.async.cg.shared.global [%0], [%1], 16;" :: "r"(saddr), "l"(g) : "memory");
}
#define CP_COMMIT() asm volatile("cp.async.commit_group;" ::: "memory")
#define CP_WAIT0()  asm volatile("cp.async.wait_group 0;" ::: "memory")
__device__ __forceinline__ void stcs4(float4* p, float4 v) {
    asm volatile("st.global.cs.v4.f32 [%0], {%1,%2,%3,%4};"
        :: "l"(p), "f"(v.x), "f"(v.y), "f"(v.z), "f"(v.w) : "memory");
}

// ---------------------------------------------------------------------------
// init: b' = bf16(cb/std), scOff, c2half, denorm codebook, instd, zero losses
__global__ void init_kernel(const float* __restrict__ std_, const float* __restrict__ mean_,
                            const float4* __restrict__ cb4) {
    __shared__ float red[128];
    __shared__ float red2[128];
    int n = blockIdx.x, t = threadIdx.x;
    float4 v = cb4[(size_t)n * 128 + t];
    float4 sd = ((const float4*)std_)[t];
    float4 mn = ((const float4*)mean_)[t];
    float4 iv = make_float4(1.0f / sd.x, 1.0f / sd.y, 1.0f / sd.z, 1.0f / sd.w);
    float4 cp = make_float4(v.x * iv.x, v.y * iv.y, v.z * iv.z, v.w * iv.w);
    ((uint2*)g_cbB)[(size_t)n * 128 + t] = make_uint2(pack_bf16(cp.x, cp.y), pack_bf16(cp.z, cp.w));
    float4 dn;
    dn.x = __fadd_rn(__fmul_rn(v.x, sd.x), mn.x);
    dn.y = __fadd_rn(__fmul_rn(v.y, sd.y), mn.y);
    dn.z = __fadd_rn(__fmul_rn(v.z, sd.z), mn.z);
    dn.w = __fadd_rn(__fmul_rn(v.w, sd.w), mn.w);
    ((float4*)g_cbD)[(size_t)n * 128 + t] = dn;
    red[t]  = v.x * v.x + v.y * v.y + v.z * v.z + v.w * v.w;
    red2[t] = mn.x * cp.x + mn.y * cp.y + mn.z * cp.z + mn.w * cp.w;
    __syncthreads();
    for (int o = 64; o > 0; o >>= 1) {
        if (t < o) { red[t] += red[t + o]; red2[t] += red2[t + o]; }
        __syncthreads();
    }
    if (t == 0) {
        g_c2half[n] = 0.5f * red[0];
        g_scOff[n]  = red2[0] + 0.5f * red[0];
    }
    if (n < 4) { int d = n * 128 + t; g_instd[d] = 1.0f / std_[d]; }
    if (n == 0 && t == 0) { g_lossU = 0.0f; g_lossK = 0.0f; g_done = 0; }
}

// MLP selector: grid BB, 512 threads (64 chunks per batch)
__global__ void mlp_kernel(const float* __restrict__ w1, const float* __restrict__ b1,
                           const float* __restrict__ w2, const float* __restrict__ b2,
                           float* __restrict__ out, int extras) {
    __shared__ float pooled[DD];
    __shared__ float hpart[512];
    __shared__ float r0[256];
    __shared__ float r1[256];
    int b = blockIdx.x, t = threadIdx.x;

    {
        float s = 0.f;
        const float* p = g_partial + (size_t)b * 64 * DD + t;
        #pragma unroll 8
        for (int c = 0; c < 64; ++c) s += p[(size_t)c * DD];
        pooled[t] = s * (1.0f / (float)SS);
    }
    __syncthreads();

    int h = t & 255, half = t >> 8;
    float acc = 0.f;
    const float* w = w1 + (size_t)(half * 256) * 256 + h;
    const float* pl = pooled + half * 256;
    #pragma unroll 8
    for (int d = 0; d < 256; ++d) acc += pl[d] * w[(size_t)d * 256];
    hpart[t] = acc;
    __syncthreads();

    if (t < 256) {
        float hv = fmaxf(hpart[t] + hpart[t + 256] + b1[t], 0.f);
        r0[t] = hv * w2[t * 2 + 0];
        r1[t] = hv * w2[t * 2 + 1];
    }
    __syncthreads();
    for (int s = 128; s > 0; s >>= 1) {
        if (t < s) { r0[t] += r0[t + s]; r1[t] += r1[t + s]; }
        __syncthreads();
    }
    if (t == 0) {
        float l0 = r0[0] + b2[0];
        float l1 = r1[0] + b2[1];
        float mx = fmaxf(l0, l1);
        float e0 = expf(l0 - mx), e1 = expf(l1 - mx);
        float inv = 1.0f / (e0 + e1);
        g_weights[b * 2 + 0] = e0 * inv;
        g_weights[b * 2 + 1] = e1 * inv;
        if (extras) {
            out[(size_t)QSIZE + 1 + BS + b * 2 + 0] = e0 * inv;
            out[(size_t)QSIZE + 1 + BS + b * 2 + 1] = e1 * inv;
        }
    }
}

// ---------------------------------------------------------------------------
// Main kernel: GEMM + argmax + pooled partials. 1024 blocks x 256 thr, 2 CTA/SM.
// M=64, K-chunk 64, double-buffered B via cp.async, row stride 144.
#define OFF_A0   0        // 64*144  = 9216
#define OFF_A1   9216
#define OFF_B0   18432    // 256*144 = 36864
#define OFF_B1   55296
#define OFF_C2   92160    // 256 f (scOff)
#define OFF_MW   93184    // 512 f
#define OFF_MV   95232    // 64 f
#define OFF_CC   95488    // 64 i
#define OFF_CAND 95744    // 512 i
#define OFF_POOL 97792    // 512 f
#define SM_TOTAL 99840

__global__ void __launch_bounds__(256, 2)
main_kernel(const float* __restrict__ x, const float* __restrict__ cb,
            const float* __restrict__ mean_) {
    extern __shared__ char smc[];
    float* c2s  = (float*)(smc + OFF_C2);
    float* maxw = (float*)(smc + OFF_MW);
    float* maxv = (float*)(smc + OFF_MV);
    int*   ccnt = (int*)(smc + OFF_CC);
    int*   cand = (int*)(smc + OFF_CAND);
    float* pool = (float*)(smc + OFF_POOL);

    const uint32_t sb = smem_u32(smc);
    const int tid  = threadIdx.x;
    const int wid  = tid >> 5;
    const int lane = tid & 31;
    const int g    = lane >> 2;
    const int t4   = lane & 3;
    const int blk = blockIdx.x;
    const size_t tokenBase = (size_t)blk * 64;

    const float4* x4 = (const float4*)x;

    c2s[tid] = g_scOff[tid];
    pool[tid] = 0.f;
    pool[256 + tid] = 0.f;
    __syncthreads();

    float acc[4][4][4];
    #pragma unroll
    for (int i = 0; i < 4; ++i)
        #pragma unroll
        for (int j = 0; j < 4; ++j)
            #pragma unroll
            for (int c = 0; c < 4; ++c) acc[i][j][c] = 0.f;

    const int rA = (lane & 7) + ((lane >> 3) & 1) * 8;
    const int cA = (lane >> 4) * 8;
    const int rB = lane & 7;
    const int cB = ((lane >> 3) & 1) * 8;

    const uint32_t b0u = sb + OFF_B0;
    const uint32_t b1u = sb + OFF_B1;
    {
        #pragma unroll
        for (int i = 0; i < 8; ++i) {
            int u = tid + i * 256;
            int row = u >> 3, c4 = u & 7;
            cp_async16(b0u + (uint32_t)(row * 144 + c4 * 16),
                       (const void*)(g_cbB + (size_t)row * 512 + c4 * 8));
        }
        CP_COMMIT();
    }
    float4 pa[4];
    #pragma unroll
    for (int i = 0; i < 4; ++i) {
        int u = tid + i * 256;
        pa[i] = x4[(tokenBase + (u >> 4)) * 128 + (u & 15)];
    }

    const int c4p = tid & 15;

    for (int kc = 0; kc < 8; ++kc) {
        char* aB = smc + ((kc & 1) ? OFF_A1 : OFF_A0);
        uint32_t aBu = sb + ((kc & 1) ? OFF_A1 : OFF_A0);
        uint32_t bBu = sb + ((kc & 1) ? OFF_B1 : OFF_B0);

        // store A: raw x -> bf16 (normalization folded into B)
        #pragma unroll
        for (int i = 0; i < 4; ++i) {
            int u = tid + i * 256;
            int row = u >> 4;
            uint2 o = make_uint2(pack_bf16(pa[i].x, pa[i].y), pack_bf16(pa[i].z, pa[i].w));
            *(uint2*)(aB + row * 144 + c4p * 8) = o;
        }
        // pooled partial: pair-combine lanes (tid, tid^16) then 16-lane atomics
        {
            float sx = pa[0].x + pa[1].x + pa[2].x + pa[3].x;
            float sy = pa[0].y + pa[1].y + pa[2].y + pa[3].y;
            float sz = pa[0].z + pa[1].z + pa[2].z + pa[3].z;
            float sw = pa[0].w + pa[1].w + pa[2].w + pa[3].w;
            sx += __shfl_xor_sync(0xffffffffu, sx, 16);
            sy += __shfl_xor_sync(0xffffffffu, sy, 16);
            sz += __shfl_xor_sync(0xffffffffu, sz, 16);
            sw += __shfl_xor_sync(0xffffffffu, sw, 16);
            if (lane < 16) {
                int d0 = (kc * 16 + c4p) * 4;
                atomicAdd(&pool[d0 + 0], sx);
                atomicAdd(&pool[d0 + 1], sy);
                atomicAdd(&pool[d0 + 2], sz);
                atomicAdd(&pool[d0 + 3], sw);
            }
        }
        CP_WAIT0();
        __syncthreads();

        if (kc < 7) {
            uint32_t nb = ((kc + 1) & 1) ? b1u : b0u;
            #pragma unroll
            for (int i = 0; i < 8; ++i) {
                int u = tid + i * 256;
                int row = u >> 3, c4 = u & 7;
                cp_async16(nb + (uint32_t)(row * 144 + c4 * 16),
                           (const void*)(g_cbB + (size_t)row * 512 + (kc + 1) * 64 + c4 * 8));
            }
            CP_COMMIT();
            #pragma unroll
            for (int i = 0; i < 4; ++i) {
                int u = tid + i * 256;
                pa[i] = x4[(tokenBase + (u >> 4)) * 128 + (kc + 1) * 16 + (u & 15)];
            }
        }

        uint32_t aAddr = aBu + (uint32_t)(rA * 144 + cA * 2);
        uint32_t bAddr = bBu + (uint32_t)((wid * 32 + rB) * 144 + cB * 2);

        #pragma unroll
        for (int kk = 0; kk < 4; ++kk) {
            const uint32_t ko = kk * 32;
            uint32_t a[4][4];
            #pragma unroll
            for (int i = 0; i < 4; ++i)
                ldmatrix_x4(a[i], aAddr + (uint32_t)(i * 16 * 144) + ko);
            #pragma unroll
            for (int j = 0; j < 4; ++j) {
                uint32_t bfr[2];
                ldmatrix_x2(bfr, bAddr + (uint32_t)(j * 8 * 144) + ko);
                #pragma unroll
                for (int i = 0; i < 4; ++i) mma_bf16(acc[i][j], a[i], bfr);
            }
        }
    }
    __syncthreads();

    g_partial[(size_t)blk * 512 + tid] = pool[tid];
    g_partial[(size_t)blk * 512 + 256 + tid] = pool[256 + tid];

    // ---- approx scores s = x.c' - scOff ; per-token max ----
    #pragma unroll
    for (int i = 0; i < 4; ++i) {
        float bv0 = -3.0e38f, bv1 = -3.0e38f;
        #pragma unroll
        for (int j = 0; j < 4; ++j) {
            int n0 = wid * 32 + j * 8 + 2 * t4;
            float s;
            s = acc[i][j][0] - c2s[n0];     if (s > bv0) bv0 = s;
            s = acc[i][j][1] - c2s[n0 + 1]; if (s > bv0) bv0 = s;
            s = acc[i][j][2] - c2s[n0];     if (s > bv1) bv1 = s;
            s = acc[i][j][3] - c2s[n0 + 1]; if (s > bv1) bv1 = s;
        }
        #pragma unroll
        for (int m = 1; m <= 2; m <<= 1) {
            bv0 = fmaxf(bv0, __shfl_xor_sync(0xffffffffu, bv0, m));
            bv1 = fmaxf(bv1, __shfl_xor_sync(0xffffffffu, bv1, m));
        }
        if (t4 == 0) {
            int r0 = i * 16 + g;
            maxw[r0 * 8 + wid] = bv0;
            maxw[(r0 + 8) * 8 + wid] = bv1;
        }
    }
    __syncthreads();
    if (tid < 64) {
        float bv = maxw[tid * 8];
        #pragma unroll
        for (int w = 1; w < 8; ++w) bv = fmaxf(bv, maxw[tid * 8 + w]);
        maxv[tid] = bv;
        ccnt[tid] = 0;
    }
    __syncthreads();

    // ---- collect candidates within MARGIN ----
    #pragma unroll
    for (int i = 0; i < 4; ++i) {
        int r0 = i * 16 + g;
        float th0 = maxv[r0] - MARGIN;
        float th1 = maxv[r0 + 8] - MARGIN;
        #pragma unroll
        for (int j = 0; j < 4; ++j) {
            int n0 = wid * 32 + j * 8 + 2 * t4;
            float s;
            s = acc[i][j][0] - c2s[n0];
            if (s >= th0) { int p = atomicAdd(&ccnt[r0], 1); if (p < 8) cand[r0 * 8 + p] = n0; }
            s = acc[i][j][1] - c2s[n0 + 1];
            if (s >= th0) { int p = atomicAdd(&ccnt[r0], 1); if (p < 8) cand[r0 * 8 + p] = n0 + 1; }
            s = acc[i][j][2] - c2s[n0];
            if (s >= th1) { int p = atomicAdd(&ccnt[r0 + 8], 1); if (p < 8) cand[(r0 + 8) * 8 + p] = n0; }
            s = acc[i][j][3] - c2s[n0 + 1];
            if (s >= th1) { int p = atomicAdd(&ccnt[r0 + 8], 1); if (p < 8) cand[(r0 + 8) * 8 + p] = n0 + 1; }
        }
    }
    __syncthreads();

    // ---- exact fp32 rescore (raw formulation): one quad per token ----
    {
        int q = tid >> 2, ql = tid & 3;
        int cnt = ccnt[q]; if (cnt > 8) cnt = 8;
        int bi;
        if (cnt == 1) {
            bi = cand[q * 8];
        } else {
            const uint32_t qmask = 0xFu << (lane & 28);
            float bs = -3.0e38f;
            bi = 1 << 30;
            const float4* xr = x4 + (tokenBase + q) * 128;
            const float4* cb4   = (const float4*)cb;
            const float4* mean4 = (const float4*)mean_;
            const float4* instd4 = (const float4*)g_instd;
            for (int ci_i = 0; ci_i < cnt; ++ci_i) {
                int ci = cand[q * 8 + ci_i];
                const float4* cr = cb4 + (size_t)ci * 128;
                float s = 0.f;
                #pragma unroll 8
                for (int k = 0; k < 32; ++k) {
                    int d4 = ql + k * 4;
                    float4 xv = xr[d4];
                    float4 cv = cr[d4];
                    float4 mn = mean4[d4];
                    float4 is = instd4[d4];
                    s += ((xv.x - mn.x) * is.x) * cv.x
                       + ((xv.y - mn.y) * is.y) * cv.y
                       + ((xv.z - mn.z) * is.z) * cv.z
                       + ((xv.w - mn.w) * is.w) * cv.w;
                }
                s += __shfl_xor_sync(qmask, s, 1);
                s += __shfl_xor_sync(qmask, s, 2);
                s -= g_c2half[ci];
                if (s > bs || (s == bs && ci < bi)) { bs = s; bi = ci; }
            }
        }
        if (ql == 0) g_sidx[tokenBase + q] = bi;
    }
}

// ---------------------------------------------------------------------------
// Epilogue: div-free FSQ + denorm-gather + combine + losses (round-12 form);
// last-arriving block writes the final loss (fused loss kernel).
__global__ void __launch_bounds__(128, 14)
epi_kernel(const float* __restrict__ x, float* __restrict__ out, int extras) {
    __shared__ int sIdx[32];
    __shared__ float red[256];
    const int tid = threadIdx.x;
    const int blk = blockIdx.x;
    const int b = blk >> 7;
    const size_t tokenBase = (size_t)blk * 32;

    const float4* x4   = (const float4*)x;
    const float4* cbD4 = (const float4*)g_cbD;

    if (tid < 32) sIdx[tid] = g_sidx[tokenBase + tid];
    const float lw0 = g_weights[b * 2 + 0];
    const float lw1 = g_weights[b * 2 + 1];
    __syncthreads();

    const float STEP = 2.0f / 7.0f;
    const float4* px = x4 + tokenBase * 128 + tid;
    float4* po = (float4*)out + tokenBase * 128 + tid;
    float du2 = 0.f, dk2 = 0.f;

    #pragma unroll 4
    for (int it = 0; it < 32; ++it) {
        float4 xv = px[it * 128];
        int ci = sIdx[it];
        float4 qk4 = cbD4[(size_t)ci * 128 + tid];
        float4 o;
        const float* xp = (const float*)&xv;
        const float* kp = (const float*)&qk4;
        float* op = (float*)&o;
        #pragma unroll
        for (int c = 0; c < 4; ++c) {
            float xx = xp[c];
            float qk = kp[c];
            float y = __fmaf_rn(xx, 3.5f, 3.5f);
            float r = rintf(y);
            float d = y - r;
            if (fabsf(d) >= 0.49995f) {
                float xcl = fminf(fmaxf(xx, -1.0f), 1.0f);
                r = rintf(__fdiv_rn(__fadd_rn(xcl, 1.0f), STEP));
            }
            r = fminf(fmaxf(r, 0.0f), 7.0f);
            float qu = __fadd_rn(__fmul_rn(r, STEP), -1.0f);
            op[c] = __fadd_rn(__fmul_rn(lw0, qu), __fmul_rn(lw1, qk));
            float du = xx - qu; du2 += du * du;
            float dk = xx - qk; dk2 += dk * dk;
        }
        stcs4(&po[it * 128], o);
    }

    red[tid] = du2;
    red[128 + tid] = dk2;
    __syncthreads();
    for (int s = 64; s > 0; s >>= 1) {
        if (tid < s) { red[tid] += red[tid + s]; red[128 + tid] += red[128 + tid + s]; }
        __syncthreads();
    }
    if (extras && tid < 32)
        out[(size_t)QSIZE + 1 + tokenBase + tid] = (float)sIdx[tid];
    if (tid == 0) {
        atomicAdd(&g_lossU, red[0]);
        atomicAdd(&g_lossK, red[128]);
        __threadfence();
        int done = atomicAdd(&g_done, 1);
        if (done == 2047) {
            float lu = atomicAdd(&g_lossU, 0.0f);
            float lk = atomicAdd(&g_lossK, 0.0f);
            out[QSIZE] = 0.25f * (lu + lk) * (1.0f / (float)QSIZE);
        }
    }
}

// ---------------------------------------------------------------------------
extern "C" void kernel_launch(void* const* d_in, const int* in_sizes, int n_in,
                              void* d_out, int out_size) {
    const float* x     = (const float*)d_in[0];
    const float* cb    = (const float*)d_in[1];
    const float* mean_ = (const float*)d_in[2];
    const float* std_  = (const float*)d_in[3];
    const float* w1    = (const float*)d_in[4];
    const float* b1    = (const float*)d_in[5];
    const float* w2    = (const float*)d_in[6];
    const float* b2    = (const float*)d_in[7];
    float* out = (float*)d_out;
    int extras = (out_size >= FULLOUT) ? 1 : 0;

    cudaFuncSetAttribute(main_kernel, cudaFuncAttributeMaxDynamicSharedMemorySize, SM_TOTAL);

    init_kernel<<<KK, 128>>>(std_, mean_, (const float4*)cb);
    main_kernel<<<BS / 64, 256, SM_TOTAL>>>(x, cb, mean_);
    mlp_kernel<<<BB, 512>>>(w1, b1, w2, b2, out, extras);
    epi_kernel<<<2048, 128>>>(x, out, extras);
}

// round 17
// speedup vs baseline: 1.4275x; 1.4275x over previous
#include <cuda_runtime.h>
#include <cuda_bf16.h>
#include <cstdint>
#include <cstddef>

// Problem constants
#define BB   16
#define SS   4096
#define DD   512
#define KK   256
#define BS   65536
#define QSIZE 33554432
#define FULLOUT (QSIZE + 1 + BS + BB*2)

#define MARGIN 1.0f

// ---------------------------------------------------------------------------
// device scratch (no cudaMalloc allowed)
__device__ float g_partial[1024 * DD];     // per-main-block pooled partials
__device__ float g_weights[BB * 2];
__device__ float g_c2half[KK];             // 0.5||c||^2 (exact rescore)
__device__ float g_scOff[KK];              // sum(m*c/s) + 0.5||c||^2 (approx score)
__device__ __align__(16) float g_instd[DD];
__device__ float g_lossU;
__device__ float g_lossK;
__device__ int   g_done;
__device__ int   g_sidx[BS];
__device__ __align__(16) __nv_bfloat16 g_cbB[KK * DD];  // bf16(cb/std)
__device__ __align__(16) float g_cbD[KK * DD];          // denormalized codebook

// ---------------------------------------------------------------------------
__device__ __forceinline__ uint32_t pack_bf16(float a, float b) {
    uint32_t r;
    asm("cvt.rn.bf16x2.f32 %0, %1, %2;" : "=r"(r) : "f"(b), "f"(a));
    return r;
}
__device__ __forceinline__ void mma_bf16(float c[4], const uint32_t a[4], const uint32_t b[2]) {
    asm volatile("mma.sync.aligned.m16n8k16.row.col.f32.bf16.bf16.f32 "
        "{%0,%1,%2,%3}, {%4,%5,%6,%7}, {%8,%9}, {%0,%1,%2,%3};"
        : "+f"(c[0]), "+f"(c[1]), "+f"(c[2]), "+f"(c[3])
        : "r"(a[0]), "r"(a[1]), "r"(a[2]), "r"(a[3]), "r"(b[0]), "r"(b[1]));
}
__device__ __forceinline__ void ldmatrix_x4(uint32_t r[4], uint32_t saddr) {
    asm volatile("ldmatrix.sync.aligned.m8n8.x4.shared.b16 {%0,%1,%2,%3}, [%4];"
        : "=r"(r[0]), "=r"(r[1]), "=r"(r[2]), "=r"(r[3]) : "r"(saddr));
}
__device__ __forceinline__ void ldmatrix_x2(uint32_t r[2], uint32_t saddr) {
    asm volatile("ldmatrix.sync.aligned.m8n8.x2.shared.b16 {%0,%1}, [%2];"
        : "=r"(r[0]), "=r"(r[1]) : "r"(saddr));
}
__device__ __forceinline__ uint32_t smem_u32(const void* p) {
    uint32_t a;
    asm("{ .reg .u64 t; cvta.to.shared.u64 t, %1; cvt.u32.u64 %0, t; }" : "=r"(a) : "l"(p));
    return a;
}
__device__ __forceinline__ void cp_async16(uint32_t saddr, const void* g) {
    asm volatile("cp.async.cg.shared.global [%0], [%1], 16;" :: "r"(saddr), "l"(g) : "memory");
}
#define CP_COMMIT() asm volatile("cp.async.commit_group;" ::: "memory")
#define CP_WAIT0()  asm volatile("cp.async.wait_group 0;" ::: "memory")
__device__ __forceinline__ void stcs4(float4* p, float4 v) {
    asm volatile("st.global.cs.v4.f32 [%0], {%1,%2,%3,%4};"
        :: "l"(p), "f"(v.x), "f"(v.y), "f"(v.z), "f"(v.w) : "memory");
}

// ---------------------------------------------------------------------------
// init: b' = bf16(cb/std), scOff, c2half, denorm codebook, instd, zero losses
__global__ void init_kernel(const float* __restrict__ std_, const float* __restrict__ mean_,
                            const float4* __restrict__ cb4) {
    __shared__ float red[128];
    __shared__ float red2[128];
    int n = blockIdx.x, t = threadIdx.x;
    float4 v = cb4[(size_t)n * 128 + t];
    float4 sd = ((const float4*)std_)[t];
    float4 mn = ((const float4*)mean_)[t];
    float4 iv = make_float4(1.0f / sd.x, 1.0f / sd.y, 1.0f / sd.z, 1.0f / sd.w);
    float4 cp = make_float4(v.x * iv.x, v.y * iv.y, v.z * iv.z, v.w * iv.w);
    ((uint2*)g_cbB)[(size_t)n * 128 + t] = make_uint2(pack_bf16(cp.x, cp.y), pack_bf16(cp.z, cp.w));
    float4 dn;
    dn.x = __fadd_rn(__fmul_rn(v.x, sd.x), mn.x);
    dn.y = __fadd_rn(__fmul_rn(v.y, sd.y), mn.y);
    dn.z = __fadd_rn(__fmul_rn(v.z, sd.z), mn.z);
    dn.w = __fadd_rn(__fmul_rn(v.w, sd.w), mn.w);
    ((float4*)g_cbD)[(size_t)n * 128 + t] = dn;
    red[t]  = v.x * v.x + v.y * v.y + v.z * v.z + v.w * v.w;
    red2[t] = mn.x * cp.x + mn.y * cp.y + mn.z * cp.z + mn.w * cp.w;
    __syncthreads();
    for (int o = 64; o > 0; o >>= 1) {
        if (t < o) { red[t] += red[t + o]; red2[t] += red2[t + o]; }
        __syncthreads();
    }
    if (t == 0) {
        g_c2half[n] = 0.5f * red[0];
        g_scOff[n]  = red2[0] + 0.5f * red[0];
    }
    if (n < 4) { int d = n * 128 + t; g_instd[d] = 1.0f / std_[d]; }
    if (n == 0 && t == 0) { g_lossU = 0.0f; g_lossK = 0.0f; g_done = 0; }
}

// MLP selector: grid BB, 512 threads (64 chunks per batch)
__global__ void mlp_kernel(const float* __restrict__ w1, const float* __restrict__ b1,
                           const float* __restrict__ w2, const float* __restrict__ b2,
                           float* __restrict__ out, int extras) {
    __shared__ float pooled[DD];
    __shared__ float hpart[512];
    __shared__ float r0[256];
    __shared__ float r1[256];
    int b = blockIdx.x, t = threadIdx.x;

    {
        float s = 0.f;
        const float* p = g_partial + (size_t)b * 64 * DD + t;
        #pragma unroll 8
        for (int c = 0; c < 64; ++c) s += p[(size_t)c * DD];
        pooled[t] = s * (1.0f / (float)SS);
    }
    __syncthreads();

    int h = t & 255, half = t >> 8;
    float acc = 0.f;
    const float* w = w1 + (size_t)(half * 256) * 256 + h;
    const float* pl = pooled + half * 256;
    #pragma unroll 8
    for (int d = 0; d < 256; ++d) acc += pl[d] * w[(size_t)d * 256];
    hpart[t] = acc;
    __syncthreads();

    if (t < 256) {
        float hv = fmaxf(hpart[t] + hpart[t + 256] + b1[t], 0.f);
        r0[t] = hv * w2[t * 2 + 0];
        r1[t] = hv * w2[t * 2 + 1];
    }
    __syncthreads();
    for (int s = 128; s > 0; s >>= 1) {
        if (t < s) { r0[t] += r0[t + s]; r1[t] += r1[t + s]; }
        __syncthreads();
    }
    if (t == 0) {
        float l0 = r0[0] + b2[0];
        float l1 = r1[0] + b2[1];
        float mx = fmaxf(l0, l1);
        float e0 = expf(l0 - mx), e1 = expf(l1 - mx);
        float inv = 1.0f / (e0 + e1);
        g_weights[b * 2 + 0] = e0 * inv;
        g_weights[b * 2 + 1] = e1 * inv;
        if (extras) {
            out[(size_t)QSIZE + 1 + BS + b * 2 + 0] = e0 * inv;
            out[(size_t)QSIZE + 1 + BS + b * 2 + 1] = e1 * inv;
        }
    }
}

// ---------------------------------------------------------------------------
// Main kernel: GEMM + argmax + pooled partials. 1024 blocks x 256 thr, 2 CTA/SM.
// M=64, K-chunk 64, double-buffered B via cp.async, row stride 144.
#define OFF_A0   0        // 64*144  = 9216
#define OFF_A1   9216
#define OFF_B0   18432    // 256*144 = 36864
#define OFF_B1   55296
#define OFF_C2   92160    // 256 f (scOff)
#define OFF_MW   93184    // 512 f
#define OFF_MV   95232    // 64 f
#define OFF_CC   95488    // 64 i
#define OFF_CAND 95744    // 512 i
#define OFF_POOL 97792    // 512 f
#define SM_TOTAL 99840

__global__ void __launch_bounds__(256, 2)
main_kernel(const float* __restrict__ x, const float* __restrict__ cb,
            const float* __restrict__ mean_) {
    extern __shared__ char smc[];
    float* c2s  = (float*)(smc + OFF_C2);
    float* maxw = (float*)(smc + OFF_MW);
    float* maxv = (float*)(smc + OFF_MV);
    int*   ccnt = (int*)(smc + OFF_CC);
    int*   cand = (int*)(smc + OFF_CAND);
    float* pool = (float*)(smc + OFF_POOL);

    const uint32_t sb = smem_u32(smc);
    const int tid  = threadIdx.x;
    const int wid  = tid >> 5;
    const int lane = tid & 31;
    const int g    = lane >> 2;
    const int t4   = lane & 3;
    const int blk = blockIdx.x;
    const size_t tokenBase = (size_t)blk * 64;

    const float4* x4 = (const float4*)x;

    c2s[tid] = g_scOff[tid];
    pool[tid] = 0.f;
    pool[256 + tid] = 0.f;
    __syncthreads();

    float acc[4][4][4];
    #pragma unroll
    for (int i = 0; i < 4; ++i)
        #pragma unroll
        for (int j = 0; j < 4; ++j)
            #pragma unroll
            for (int c = 0; c < 4; ++c) acc[i][j][c] = 0.f;

    const int rA = (lane & 7) + ((lane >> 3) & 1) * 8;
    const int cA = (lane >> 4) * 8;
    const int rB = lane & 7;
    const int cB = ((lane >> 3) & 1) * 8;

    const uint32_t b0u = sb + OFF_B0;
    const uint32_t b1u = sb + OFF_B1;
    {
        #pragma unroll
        for (int i = 0; i < 8; ++i) {
            int u = tid + i * 256;
            int row = u >> 3, c4 = u & 7;
            cp_async16(b0u + (uint32_t)(row * 144 + c4 * 16),
                       (const void*)(g_cbB + (size_t)row * 512 + c4 * 8));
        }
        CP_COMMIT();
    }
    float4 pa[4];
    #pragma unroll
    for (int i = 0; i < 4; ++i) {
        int u = tid + i * 256;
        pa[i] = x4[(tokenBase + (u >> 4)) * 128 + (u & 15)];
    }

    const int c4p = tid & 15;

    for (int kc = 0; kc < 8; ++kc) {
        char* aB = smc + ((kc & 1) ? OFF_A1 : OFF_A0);
        uint32_t aBu = sb + ((kc & 1) ? OFF_A1 : OFF_A0);
        uint32_t bBu = sb + ((kc & 1) ? OFF_B1 : OFF_B0);

        // store A: raw x -> bf16 (normalization folded into B)
        #pragma unroll
        for (int i = 0; i < 4; ++i) {
            int u = tid + i * 256;
            int row = u >> 4;
            uint2 o = make_uint2(pack_bf16(pa[i].x, pa[i].y), pack_bf16(pa[i].z, pa[i].w));
            *(uint2*)(aB + row * 144 + c4p * 8) = o;
        }
        // pooled partial: pair-combine lanes (tid, tid^16) then 16-lane atomics
        {
            float sx = pa[0].x + pa[1].x + pa[2].x + pa[3].x;
            float sy = pa[0].y + pa[1].y + pa[2].y + pa[3].y;
            float sz = pa[0].z + pa[1].z + pa[2].z + pa[3].z;
            float sw = pa[0].w + pa[1].w + pa[2].w + pa[3].w;
            sx += __shfl_xor_sync(0xffffffffu, sx, 16);
            sy += __shfl_xor_sync(0xffffffffu, sy, 16);
            sz += __shfl_xor_sync(0xffffffffu, sz, 16);
            sw += __shfl_xor_sync(0xffffffffu, sw, 16);
            if (lane < 16) {
                int d0 = (kc * 16 + c4p) * 4;
                atomicAdd(&pool[d0 + 0], sx);
                atomicAdd(&pool[d0 + 1], sy);
                atomicAdd(&pool[d0 + 2], sz);
                atomicAdd(&pool[d0 + 3], sw);
            }
        }
        CP_WAIT0();
        __syncthreads();

        if (kc < 7) {
            uint32_t nb = ((kc + 1) & 1) ? b1u : b0u;
            #pragma unroll
            for (int i = 0; i < 8; ++i) {
                int u = tid + i * 256;
                int row = u >> 3, c4 = u & 7;
                cp_async16(nb + (uint32_t)(row * 144 + c4 * 16),
                           (const void*)(g_cbB + (size_t)row * 512 + (kc + 1) * 64 + c4 * 8));
            }
            CP_COMMIT();
            #pragma unroll
            for (int i = 0; i < 4; ++i) {
                int u = tid + i * 256;
                pa[i] = x4[(tokenBase + (u >> 4)) * 128 + (kc + 1) * 16 + (u & 15)];
            }
        }

        uint32_t aAddr = aBu + (uint32_t)(rA * 144 + cA * 2);
        uint32_t bAddr = bBu + (uint32_t)((wid * 32 + rB) * 144 + cB * 2);

        #pragma unroll
        for (int kk = 0; kk < 4; ++kk) {
            const uint32_t ko = kk * 32;
            uint32_t a[4][4];
            #pragma unroll
            for (int i = 0; i < 4; ++i)
                ldmatrix_x4(a[i], aAddr + (uint32_t)(i * 16 * 144) + ko);
            #pragma unroll
            for (int j = 0; j < 4; ++j) {
                uint32_t bfr[2];
                ldmatrix_x2(bfr, bAddr + (uint32_t)(j * 8 * 144) + ko);
                #pragma unroll
                for (int i = 0; i < 4; ++i) mma_bf16(acc[i][j], a[i], bfr);
            }
        }
    }
    __syncthreads();

    g_partial[(size_t)blk * 512 + tid] = pool[tid];
    g_partial[(size_t)blk * 512 + 256 + tid] = pool[256 + tid];

    // ---- approx scores s = x.c' - scOff ; per-token max ----
    #pragma unroll
    for (int i = 0; i < 4; ++i) {
        float bv0 = -3.0e38f, bv1 = -3.0e38f;
        #pragma unroll
        for (int j = 0; j < 4; ++j) {
            int n0 = wid * 32 + j * 8 + 2 * t4;
            float s;
            s = acc[i][j][0] - c2s[n0];     if (s > bv0) bv0 = s;
            s = acc[i][j][1] - c2s[n0 + 1]; if (s > bv0) bv0 = s;
            s = acc[i][j][2] - c2s[n0];     if (s > bv1) bv1 = s;
            s = acc[i][j][3] - c2s[n0 + 1]; if (s > bv1) bv1 = s;
        }
        #pragma unroll
        for (int m = 1; m <= 2; m <<= 1) {
            bv0 = fmaxf(bv0, __shfl_xor_sync(0xffffffffu, bv0, m));
            bv1 = fmaxf(bv1, __shfl_xor_sync(0xffffffffu, bv1, m));
        }
        if (t4 == 0) {
            int r0 = i * 16 + g;
            maxw[r0 * 8 + wid] = bv0;
            maxw[(r0 + 8) * 8 + wid] = bv1;
        }
    }
    __syncthreads();
    if (tid < 64) {
        float bv = maxw[tid * 8];
        #pragma unroll
        for (int w = 1; w < 8; ++w) bv = fmaxf(bv, maxw[tid * 8 + w]);
        maxv[tid] = bv;
        ccnt[tid] = 0;
    }
    __syncthreads();

    // ---- collect candidates within MARGIN ----
    #pragma unroll
    for (int i = 0; i < 4; ++i) {
        int r0 = i * 16 + g;
        float th0 = maxv[r0] - MARGIN;
        float th1 = maxv[r0 + 8] - MARGIN;
        #pragma unroll
        for (int j = 0; j < 4; ++j) {
            int n0 = wid * 32 + j * 8 + 2 * t4;
            float s;
            s = acc[i][j][0] - c2s[n0];
            if (s >= th0) { int p = atomicAdd(&ccnt[r0], 1); if (p < 8) cand[r0 * 8 + p] = n0; }
            s = acc[i][j][1] - c2s[n0 + 1];
            if (s >= th0) { int p = atomicAdd(&ccnt[r0], 1); if (p < 8) cand[r0 * 8 + p] = n0 + 1; }
            s = acc[i][j][2] - c2s[n0];
            if (s >= th1) { int p = atomicAdd(&ccnt[r0 + 8], 1); if (p < 8) cand[(r0 + 8) * 8 + p] = n0; }
            s = acc[i][j][3] - c2s[n0 + 1];
            if (s >= th1) { int p = atomicAdd(&ccnt[r0 + 8], 1); if (p < 8) cand[(r0 + 8) * 8 + p] = n0 + 1; }
        }
    }
    __syncthreads();

    // ---- exact fp32 rescore (raw formulation): one quad per token ----
    {
        int q = tid >> 2, ql = tid & 3;
        int cnt = ccnt[q]; if (cnt > 8) cnt = 8;
        int bi;
        if (cnt == 1) {
            bi = cand[q * 8];
        } else {
            const uint32_t qmask = 0xFu << (lane & 28);
            float bs = -3.0e38f;
            bi = 1 << 30;
            const float4* xr = x4 + (tokenBase + q) * 128;
            const float4* cb4   = (const float4*)cb;
            const float4* mean4 = (const float4*)mean_;
            const float4* instd4 = (const float4*)g_instd;
            for (int ci_i = 0; ci_i < cnt; ++ci_i) {
                int ci = cand[q * 8 + ci_i];
                const float4* cr = cb4 + (size_t)ci * 128;
                float s = 0.f;
                #pragma unroll 8
                for (int k = 0; k < 32; ++k) {
                    int d4 = ql + k * 4;
                    float4 xv = xr[d4];
                    float4 cv = cr[d4];
                    float4 mn = mean4[d4];
                    float4 is = instd4[d4];
                    s += ((xv.x - mn.x) * is.x) * cv.x
                       + ((xv.y - mn.y) * is.y) * cv.y
                       + ((xv.z - mn.z) * is.z) * cv.z
                       + ((xv.w - mn.w) * is.w) * cv.w;
                }
                s += __shfl_xor_sync(qmask, s, 1);
                s += __shfl_xor_sync(qmask, s, 2);
                s -= g_c2half[ci];
                if (s > bs || (s == bs && ci < bi)) { bs = s; bi = ci; }
            }
        }
        if (ql == 0) g_sidx[tokenBase + q] = bi;
    }
}

// ---------------------------------------------------------------------------
// Epilogue: div-free FSQ + denorm-gather + combine + losses;
// last-arriving block writes the final loss (fused loss kernel).
__global__ void __launch_bounds__(128, 14)
epi_kernel(const float* __restrict__ x, float* __restrict__ out, int extras) {
    __shared__ int sIdx[32];
    __shared__ float red[256];
    const int tid = threadIdx.x;
    const int blk = blockIdx.x;
    const int b = blk >> 7;
    const size_t tokenBase = (size_t)blk * 32;

    const float4* x4   = (const float4*)x;
    const float4* cbD4 = (const float4*)g_cbD;

    if (tid < 32) sIdx[tid] = g_sidx[tokenBase + tid];
    const float lw0 = g_weights[b * 2 + 0];
    const float lw1 = g_weights[b * 2 + 1];
    __syncthreads();

    const float STEP = 2.0f / 7.0f;
    const float4* px = x4 + tokenBase * 128 + tid;
    float4* po = (float4*)out + tokenBase * 128 + tid;
    float du2 = 0.f, dk2 = 0.f;

    #pragma unroll 4
    for (int it = 0; it < 32; ++it) {
        float4 xv = px[it * 128];
        int ci = sIdx[it];
        float4 qk4 = cbD4[(size_t)ci * 128 + tid];
        float4 o;
        const float* xp = (const float*)&xv;
        const float* kp = (const float*)&qk4;
        float* op = (float*)&o;
        #pragma unroll
        for (int c = 0; c < 4; ++c) {
            float xx = xp[c];
            float qk = kp[c];
            float y = __fmaf_rn(xx, 3.5f, 3.5f);
            float r = rintf(y);
            float d = y - r;
            if (fabsf(d) >= 0.49995f) {
                float xcl = fminf(fmaxf(xx, -1.0f), 1.0f);
                r = rintf(__fdiv_rn(__fadd_rn(xcl, 1.0f), STEP));
            }
            r = fminf(fmaxf(r, 0.0f), 7.0f);
            float qu = __fadd_rn(__fmul_rn(r, STEP), -1.0f);
            op[c] = __fadd_rn(__fmul_rn(lw0, qu), __fmul_rn(lw1, qk));
            float du = xx - qu; du2 += du * du;
            float dk = xx - qk; dk2 += dk * dk;
        }
        stcs4(&po[it * 128], o);
    }

    red[tid] = du2;
    red[128 + tid] = dk2;
    __syncthreads();
    for (int s = 64; s > 0; s >>= 1) {
        if (tid < s) { red[tid] += red[tid + s]; red[128 + tid] += red[128 + tid + s]; }
        __syncthreads();
    }
    if (extras && tid < 32)
        out[(size_t)QSIZE + 1 + tokenBase + tid] = (float)sIdx[tid];
    if (tid == 0) {
        atomicAdd(&g_lossU, red[0]);
        atomicAdd(&g_lossK, red[128]);
        __threadfence();
        int done = atomicAdd(&g_done, 1);
        if (done == 2047) {
            float lu = atomicAdd(&g_lossU, 0.0f);
            float lk = atomicAdd(&g_lossK, 0.0f);
            out[QSIZE] = 0.25f * (lu + lk) * (1.0f / (float)QSIZE);
        }
    }
}

// ---------------------------------------------------------------------------
extern "C" void kernel_launch(void* const* d_in, const int* in_sizes, int n_in,
                              void* d_out, int out_size) {
    const float* x     = (const float*)d_in[0];
    const float* cb    = (const float*)d_in[1];
    const float* mean_ = (const float*)d_in[2];
    const float* std_  = (const float*)d_in[3];
    const float* w1    = (const float*)d_in[4];
    const float* b1    = (const float*)d_in[5];
    const float* w2    = (const float*)d_in[6];
    const float* b2    = (const float*)d_in[7];
    float* out = (float*)d_out;
    int extras = (out_size >= FULLOUT) ? 1 : 0;

    cudaFuncSetAttribute(main_kernel, cudaFuncAttributeMaxDynamicSharedMemorySize, SM_TOTAL);

    init_kernel<<<KK, 128>>>(std_, mean_, (const float4*)cb);
    main_kernel<<<BS / 64, 256, SM_TOTAL>>>(x, cb, mean_);
    mlp_kernel<<<BB, 512>>>(w1, b1, w2, b2, out, extras);
    epi_kernel<<<2048, 128>>>(x, out, extras);
}